// round 3
// baseline (speedup 1.0000x reference)
#include <cuda_runtime.h>

// WindowAttention3D fused kernel (fp32, one CTA per window).
// Shapes: B=4096 windows, N=98 tokens, C=96, H=3 heads, hd=32.

#define N_TOK 98
#define C_DIM 96
#define NHEAD 3
#define HD    32
#define NWIN  4096
#define XLD   97      // x_s / y_s / z_s row stride (rows=lane, stride 97 -> conflict-free)
#define KLD   101     // qT/kT/vT row stride over n (lane stride 101 -> (5*lane)%32 distinct)
#define ALD   104     // per-warp attention-prob buffer stride

#define NTHREADS 512
#define NWARPS   16

// SMEM float offsets
#define X_OFF 0                      // 98*97   = 9506
#define Q_OFF 9506                   // 96*101  = 9696
#define K_OFF 19202
#define V_OFF 28898
#define A_OFF 38594                  // 16*104  = 1664
#define SMEM_FLOATS 40258
#define SMEM_BYTES  (SMEM_FLOATS * 4)

// Precomputed bias[h][n][m] (115 KB, L2-resident across all 4096 blocks)
__device__ float g_bias[NHEAD * N_TOK * N_TOK];

__global__ void bias_precompute_kernel(const float* __restrict__ table,
                                       const int* __restrict__ ridx) {
    int i = blockIdx.x * blockDim.x + threadIdx.x;
    if (i < NHEAD * N_TOK * N_TOK) {
        int h  = i / (N_TOK * N_TOK);
        int nm = i % (N_TOK * N_TOK);
        g_bias[i] = table[ridx[nm] * NHEAD + h];
    }
}

__global__ void __launch_bounds__(NTHREADS, 1)
win_attn_kernel(const float* __restrict__ x,
                const float* __restrict__ qkv_w,   // [288][96]
                const float* __restrict__ qkv_b,   // [288]
                const float* __restrict__ proj_w,  // [96][96]
                const float* __restrict__ proj_b,  // [96]
                float* __restrict__ out) {
    extern __shared__ float sm[];
    float* x_s = sm + X_OFF;   // [98][XLD]  x, later reused as y (attn output)
    float* qT  = sm + Q_OFF;   // [96][KLD]  row = h*32+d, col = n; later reused as z_s
    float* kT  = sm + K_OFF;
    float* vT  = sm + V_OFF;
    float* at  = sm + A_OFF;   // [16][ALD]

    const int tid  = threadIdx.x;
    const int lane = tid & 31;
    const int warp = tid >> 5;
    const int b    = blockIdx.x;
    const float* xb = x + (size_t)b * (N_TOK * C_DIM);

    // ---------------- Phase 1: load x (coalesced float4 LDG) ----------------
    for (int idx = tid * 4; idx < N_TOK * C_DIM; idx += NTHREADS * 4) {
        float4 v = *(const float4*)(xb + idx);
        int n = idx / C_DIM, k = idx % C_DIM;       // k%4==0, never crosses a row
        float* dst = x_s + n * XLD + k;
        dst[0] = v.x; dst[1] = v.y; dst[2] = v.z; dst[3] = v.w;
    }
    __syncthreads();

    // ---------------- Phase 2: QKV GEMM [98,96]x[96,288] -------------------
    // warp -> 18 output cols (3 groups of 6); lane -> rows {lane, lane+32, lane+64}
    {
        const int r0 = lane, r1 = lane + 32, r2 = lane + 64;
        for (int g = 0; g < 3; ++g) {
            const int jb = warp * 18 + g * 6;
            float a0[6], a1[6], a2[6];
            #pragma unroll
            for (int c = 0; c < 6; ++c) { a0[c] = 0.f; a1[c] = 0.f; a2[c] = 0.f; }
            const float* wp = qkv_w + jb * C_DIM;
            #pragma unroll 4
            for (int k = 0; k < C_DIM; ++k) {
                float x0 = x_s[r0 * XLD + k];   // lane stride 97 -> conflict-free
                float x1 = x_s[r1 * XLD + k];
                float x2 = x_s[r2 * XLD + k];
                #pragma unroll
                for (int c = 0; c < 6; ++c) {
                    float wv = __ldg(wp + c * C_DIM + k);   // warp-uniform
                    a0[c] += x0 * wv; a1[c] += x1 * wv; a2[c] += x2 * wv;
                }
            }
            #pragma unroll
            for (int c = 0; c < 6; ++c) {
                int j   = jb + c;
                float bv = qkv_b[j];
                int mat = j / C_DIM;           // 0=q 1=k 2=v
                int jj  = j % C_DIM;           // h*32+d
                float* base = (mat == 0) ? qT : (mat == 1) ? kT : vT;
                float* dst  = base + jj * KLD; // lanes write consecutive n -> conflict-free
                dst[r0] = a0[c] + bv;
                dst[r1] = a1[c] + bv;
                dst[r2] = a2[c] + bv;
            }
        }
        // rows 96,97: one column per thread (288 threads)
        if (tid < 3 * C_DIM) {
            int j = tid;
            float s0 = 0.f, s1 = 0.f;
            const float* wp = qkv_w + j * C_DIM;
            #pragma unroll 4
            for (int k = 0; k < C_DIM; ++k) {
                float wv = __ldg(wp + k);      // per-lane j -> coalesced
                s0 += x_s[96 * XLD + k] * wv;  // broadcast
                s1 += x_s[97 * XLD + k] * wv;
            }
            float bv = qkv_b[j];
            int mat = j / C_DIM, jj = j % C_DIM;
            float* base = (mat == 0) ? qT : (mat == 1) ? kT : vT;
            base[jj * KLD + 96] = s0 + bv;
            base[jj * KLD + 97] = s1 + bv;
        }
    }
    __syncthreads();

    // ---------------- Phase 3: attention (warp per (h, n) row) -------------
    const float scale = 0.1767766952966369f;   // 32^-0.5
    for (int t = warp; t < NHEAD * N_TOK; t += NWARPS) {
        const int h = t / N_TOK;
        const int n = t % N_TOK;
        const float* qrow  = qT + (h * HD) * KLD + n;   // q[d] at qrow[d*KLD] (broadcast)
        const float* kbase = kT + (h * HD) * KLD;
        const int m0 = lane, m1 = lane + 32, m2 = lane + 64, m3 = lane + 96;
        const bool v3 = (m3 < N_TOK);
        const int m3s = v3 ? m3 : 0;
        float s0 = 0.f, s1 = 0.f, s2 = 0.f, s3 = 0.f;
        #pragma unroll 8
        for (int d = 0; d < HD; ++d) {
            float qv = qrow[d * KLD];
            const float* kr = kbase + d * KLD;   // lanes m consecutive -> conflict-free
            s0 += qv * kr[m0];
            s1 += qv * kr[m1];
            s2 += qv * kr[m2];
            s3 += qv * kr[m3s];
        }
        const float* brow = g_bias + (h * N_TOK + n) * N_TOK;  // coalesced
        s0 = s0 * scale + brow[m0];
        s1 = s1 * scale + brow[m1];
        s2 = s2 * scale + brow[m2];
        s3 = v3 ? (s3 * scale + brow[m3]) : -1e30f;
        float mx = fmaxf(fmaxf(s0, s1), fmaxf(s2, s3));
        #pragma unroll
        for (int o = 16; o; o >>= 1) mx = fmaxf(mx, __shfl_xor_sync(0xffffffffu, mx, o));
        float e0 = __expf(s0 - mx), e1 = __expf(s1 - mx), e2 = __expf(s2 - mx);
        float e3 = v3 ? __expf(s3 - mx) : 0.f;
        float sum = e0 + e1 + e2 + e3;
        #pragma unroll
        for (int o = 16; o; o >>= 1) sum += __shfl_xor_sync(0xffffffffu, sum, o);
        float inv = 1.0f / sum;
        float* arow = at + warp * ALD;
        arow[m0] = e0 * inv;
        arow[m1] = e1 * inv;
        arow[m2] = e2 * inv;
        if (v3) arow[m3] = e3 * inv;
        __syncwarp();
        // AV: lane = d (hd == warpsize)
        const float* vrow = vT + (h * HD + lane) * KLD;  // lane stride 101 -> conflict-free
        float o = 0.f;
        #pragma unroll 2
        for (int m = 0; m < N_TOK; ++m)
            o += arow[m] * vrow[m];                      // arow[m] broadcast
        x_s[n * XLD + h * HD + lane] = o;                // y[n][h*32+d], lanes consecutive
        __syncwarp();                                    // protect arow before next task
    }
    __syncthreads();

    // ---------------- Phase 4: proj [98,96]x[96,96] + bias ------------------
    float* z_s = qT;   // reuse (9696 floats >= 98*97=9506), stride XLD
    {
        const int r0 = lane, r1 = lane + 32, r2 = lane + 64;
        const int cb = warp * 6;                  // 16 warps * 6 = 96 cols
        float a0[6], a1[6], a2[6];
        #pragma unroll
        for (int c = 0; c < 6; ++c) { a0[c] = 0.f; a1[c] = 0.f; a2[c] = 0.f; }
        const float* wp = proj_w + cb * C_DIM;
        #pragma unroll 4
        for (int k = 0; k < C_DIM; ++k) {
            float x0 = x_s[r0 * XLD + k];
            float x1 = x_s[r1 * XLD + k];
            float x2 = x_s[r2 * XLD + k];
            #pragma unroll
            for (int c = 0; c < 6; ++c) {
                float wv = __ldg(wp + c * C_DIM + k);
                a0[c] += x0 * wv; a1[c] += x1 * wv; a2[c] += x2 * wv;
            }
        }
        #pragma unroll
        for (int c = 0; c < 6; ++c) {
            float pb = proj_b[cb + c];
            z_s[r0 * XLD + cb + c] = a0[c] + pb;
            z_s[r1 * XLD + cb + c] = a1[c] + pb;
            z_s[r2 * XLD + cb + c] = a2[c] + pb;
        }
        if (tid < 2 * C_DIM) {        // rows 96,97
            int c = tid % C_DIM;
            int r = 96 + tid / C_DIM;
            float a = 0.f;
            const float* wp2 = proj_w + c * C_DIM;
            #pragma unroll 4
            for (int k = 0; k < C_DIM; ++k)
                a += x_s[r * XLD + k] * __ldg(wp2 + k);
            z_s[r * XLD + c] = a + proj_b[c];
        }
    }
    __syncthreads();

    // ---------------- Phase 5: coalesced float4 store -----------------------
    float* ob = out + (size_t)b * (N_TOK * C_DIM);
    for (int idx = tid * 4; idx < N_TOK * C_DIM; idx += NTHREADS * 4) {
        int n = idx / C_DIM, k = idx % C_DIM;
        const float* src = z_s + n * XLD + k;
        float4 v = make_float4(src[0], src[1], src[2], src[3]);
        *(float4*)(ob + idx) = v;
    }
}

extern "C" void kernel_launch(void* const* d_in, const int* in_sizes, int n_in,
                              void* d_out, int out_size) {
    const float* x      = (const float*)d_in[0];
    const float* qkv_w  = (const float*)d_in[1];
    const float* qkv_b  = (const float*)d_in[2];
    const float* proj_w = (const float*)d_in[3];
    const float* proj_b = (const float*)d_in[4];
    const float* table  = (const float*)d_in[5];
    const int*   ridx   = (const int*)d_in[6];
    float* out = (float*)d_out;

    bias_precompute_kernel<<<(NHEAD * N_TOK * N_TOK + 255) / 256, 256>>>(table, ridx);

    cudaFuncSetAttribute(win_attn_kernel,
                         cudaFuncAttributeMaxDynamicSharedMemorySize, SMEM_BYTES);
    win_attn_kernel<<<NWIN, NTHREADS, SMEM_BYTES>>>(x, qkv_w, qkv_b, proj_w, proj_b, out);
}

// round 6
// speedup vs baseline: 1.7876x; 1.7876x over previous
#include <cuda_runtime.h>

// WindowAttention3D fused kernel (fp32, one CTA per window), round 4:
// fully 128-bit vectorized smem/L1 traffic + 4x register-tiled attention.
// Shapes: B=4096 windows, N=98 tokens, C=96, H=3 heads, hd=32.

#define N_TOK 98
#define C_DIM 96
#define NHEAD 3
#define HD    32
#define NWIN  4096
#define XLD   100     // x/z row stride (25 16B-units, 25%8==1 -> LDS.128 conflict-free)
#define KLD   100     // qT/kT/vT row stride over n (same property)
#define ALD   100     // per-warp prob rows

#define NTHREADS 512
#define NWARPS   16

// SMEM float offsets
#define X_OFF 0                       // 98*100  = 9800
#define Q_OFF 9800                    // 96*100  = 9600
#define K_OFF 19400
#define V_OFF 29000
#define A_OFF 38600                   // 16 warps * 4 rows * 100 = 6400
#define SMEM_FLOATS 45000
#define SMEM_BYTES  (SMEM_FLOATS * 4)

// Precomputed bias[h][n][m] (115 KB, L2-resident across all 4096 blocks)
__device__ float g_bias[NHEAD * N_TOK * N_TOK];

__global__ void bias_precompute_kernel(const float* __restrict__ table,
                                       const int* __restrict__ ridx) {
    int i = blockIdx.x * blockDim.x + threadIdx.x;
    if (i < NHEAD * N_TOK * N_TOK) {
        int h  = i / (N_TOK * N_TOK);
        int nm = i % (N_TOK * N_TOK);
        g_bias[i] = table[ridx[nm] * NHEAD + h];
    }
}

__device__ __forceinline__ float4 ldg4(const float* p) {
    return __ldg((const float4*)p);
}

__global__ void __launch_bounds__(NTHREADS, 1)
win_attn_kernel(const float* __restrict__ x,
                const float* __restrict__ qkv_w,   // [288][96]
                const float* __restrict__ qkv_b,   // [288]
                const float* __restrict__ proj_w,  // [96][96]
                const float* __restrict__ proj_b,  // [96]
                float* __restrict__ out) {
    extern __shared__ float sm[];
    float* x_s = sm + X_OFF;   // [98][XLD]  x, later reused as y (attn output)
    float* qT  = sm + Q_OFF;   // [96][KLD]  row = h*32+d, col = n
    float* kT  = sm + K_OFF;
    float* vT  = sm + V_OFF;
    float* at  = sm + A_OFF;   // [NWARPS][4][ALD]

    const int tid  = threadIdx.x;
    const int lane = tid & 31;
    const int warp = tid >> 5;
    const int b    = blockIdx.x;
    const float* xb = x + (size_t)b * (N_TOK * C_DIM);

    // ---- Phase 1: load x (coalesced float4), zero pad cols 98/99 of q/k/vT
    for (int idx = tid * 4; idx < N_TOK * C_DIM; idx += NTHREADS * 4) {
        float4 v = *(const float4*)(xb + idx);
        int n = idx / C_DIM, k = idx % C_DIM;        // k%4==0, row-aligned 16B
        float4* dst = (float4*)(x_s + n * XLD + k);
        *dst = v;
    }
    if (tid < 3 * C_DIM * 2) {                       // 576 pad entries
        int mat = tid / (C_DIM * 2);
        int rc  = tid % (C_DIM * 2);
        float* base = (mat == 0) ? qT : (mat == 1) ? kT : vT;
        base[(rc >> 1) * KLD + 98 + (rc & 1)] = 0.f;
    }
    __syncthreads();

    // ---- Phase 2: QKV GEMM [98,96]x[96,288], float4 everywhere ------------
    {
        const int r0 = lane, r1 = lane + 32, r2 = lane + 64;
        for (int g = 0; g < 3; ++g) {
            const int jb = warp * 18 + g * 6;
            float a0[6], a1[6], a2[6];
            #pragma unroll
            for (int c = 0; c < 6; ++c) { a0[c] = 0.f; a1[c] = 0.f; a2[c] = 0.f; }
            const float* wp = qkv_w + jb * C_DIM;
            #pragma unroll 3
            for (int kq = 0; kq < C_DIM / 4; ++kq) {
                float4 x0 = *(const float4*)(x_s + r0 * XLD + 4 * kq);
                float4 x1 = *(const float4*)(x_s + r1 * XLD + 4 * kq);
                float4 x2 = *(const float4*)(x_s + r2 * XLD + 4 * kq);
                #pragma unroll
                for (int c = 0; c < 6; ++c) {
                    float4 wv = ldg4(wp + c * C_DIM + 4 * kq);  // warp-uniform
                    a0[c] += x0.x * wv.x + x0.y * wv.y + x0.z * wv.z + x0.w * wv.w;
                    a1[c] += x1.x * wv.x + x1.y * wv.y + x1.z * wv.z + x1.w * wv.w;
                    a2[c] += x2.x * wv.x + x2.y * wv.y + x2.z * wv.z + x2.w * wv.w;
                }
            }
            #pragma unroll
            for (int c = 0; c < 6; ++c) {
                int j   = jb + c;
                float bv = qkv_b[j];
                int mat = j / C_DIM;            // 0=q 1=k 2=v
                int jj  = j % C_DIM;            // h*32+d
                float* base = (mat == 0) ? qT : (mat == 1) ? kT : vT;
                float* dst  = base + jj * KLD;  // lanes write consecutive n
                dst[r0] = a0[c] + bv;
                dst[r1] = a1[c] + bv;
                dst[r2] = a2[c] + bv;
            }
        }
        if (tid < 3 * C_DIM) {                  // rows 96,97
            int j = tid;
            float s0 = 0.f, s1 = 0.f;
            const float* wp = qkv_w + j * C_DIM;
            #pragma unroll 6
            for (int kq = 0; kq < C_DIM / 4; ++kq) {
                float4 wv = ldg4(wp + 4 * kq);
                float4 xa = *(const float4*)(x_s + 96 * XLD + 4 * kq);
                float4 xb2 = *(const float4*)(x_s + 97 * XLD + 4 * kq);
                s0 += xa.x * wv.x + xa.y * wv.y + xa.z * wv.z + xa.w * wv.w;
                s1 += xb2.x * wv.x + xb2.y * wv.y + xb2.z * wv.z + xb2.w * wv.w;
            }
            float bv = qkv_b[j];
            int mat = j / C_DIM, jj = j % C_DIM;
            float* base = (mat == 0) ? qT : (mat == 1) ? kT : vT;
            base[jj * KLD + 96] = s0 + bv;
            base[jj * KLD + 97] = s1 + bv;
        }
    }
    __syncthreads();

    // ---- Phase 3: attention, warp per (head, 4-row quad) -------------------
    const float scale = 0.1767766952966369f;   // 32^-0.5
    const int NQUAD = (N_TOK + 3) / 4;         // 25
    for (int t = warp; t < NHEAD * NQUAD; t += NWARPS) {
        const int h  = t / NQUAD;
        const int n0 = (t % NQUAD) * 4;
        const float* qbase = qT + (h * HD) * KLD + n0;
        const float* kbase = kT + (h * HD) * KLD;

        float s[4][4];
        #pragma unroll
        for (int j = 0; j < 4; ++j)
            #pragma unroll
            for (int i = 0; i < 4; ++i) s[j][i] = 0.f;

        #pragma unroll 4
        for (int d = 0; d < HD; ++d) {
            float4 q4 = *(const float4*)(qbase + d * KLD);  // broadcast LDS.128
            const float* kr = kbase + d * KLD;
            float k0 = kr[lane];
            float k1 = kr[lane + 32];
            float k2 = kr[lane + 64];
            float k3 = kr[lane + 96];   // may read pad/garbage; masked below
            s[0][0] += q4.x * k0; s[0][1] += q4.x * k1; s[0][2] += q4.x * k2; s[0][3] += q4.x * k3;
            s[1][0] += q4.y * k0; s[1][1] += q4.y * k1; s[1][2] += q4.y * k2; s[1][3] += q4.y * k3;
            s[2][0] += q4.z * k0; s[2][1] += q4.z * k1; s[2][2] += q4.z * k2; s[2][3] += q4.z * k3;
            s[3][0] += q4.w * k0; s[3][1] += q4.w * k1; s[3][2] += q4.w * k2; s[3][3] += q4.w * k3;
        }

        float* ap = at + warp * (4 * ALD);
        const int m3 = lane + 96;
        const bool v3 = (m3 < N_TOK);
        #pragma unroll
        for (int j = 0; j < 4; ++j) {
            int n = n0 + j;
            int nc = (n < N_TOK) ? n : N_TOK - 1;   // clamp for safe bias index
            const float* brow = g_bias + (h * N_TOK + nc) * N_TOK;
            float t0 = s[j][0] * scale + brow[lane];
            float t1 = s[j][1] * scale + brow[lane + 32];
            float t2 = s[j][2] * scale + brow[lane + 64];
            float t3 = v3 ? (s[j][3] * scale + brow[m3]) : -1e30f;
            float mx = fmaxf(fmaxf(t0, t1), fmaxf(t2, t3));
            #pragma unroll
            for (int o = 16; o; o >>= 1) mx = fmaxf(mx, __shfl_xor_sync(0xffffffffu, mx, o));
            float e0 = __expf(t0 - mx), e1 = __expf(t1 - mx), e2 = __expf(t2 - mx);
            float e3 = v3 ? __expf(t3 - mx) : 0.f;
            float sum = e0 + e1 + e2 + e3;
            #pragma unroll
            for (int o = 16; o; o >>= 1) sum += __shfl_xor_sync(0xffffffffu, sum, o);
            float inv = 1.0f / sum;
            float* arow = ap + j * ALD;
            arow[lane]      = e0 * inv;
            arow[lane + 32] = e1 * inv;
            arow[lane + 64] = e2 * inv;
            if (m3 < ALD) arow[m3] = e3 * inv;   // lanes 0..3 write m=96..99 (98,99 get 0)
        }
        __syncwarp();

        // AV: lane = d; float4 over m
        const float* vrow = vT + (h * HD + lane) * KLD;
        float o0 = 0.f, o1 = 0.f, o2 = 0.f, o3 = 0.f;
        #pragma unroll 5
        for (int mq = 0; mq < ALD / 4; ++mq) {
            float4 vv = *(const float4*)(vrow + 4 * mq);   // stride 25 units -> cf
            float4 p0 = *(const float4*)(ap + 0 * ALD + 4 * mq);  // broadcasts
            float4 p1 = *(const float4*)(ap + 1 * ALD + 4 * mq);
            float4 p2 = *(const float4*)(ap + 2 * ALD + 4 * mq);
            float4 p3 = *(const float4*)(ap + 3 * ALD + 4 * mq);
            o0 += p0.x * vv.x + p0.y * vv.y + p0.z * vv.z + p0.w * vv.w;
            o1 += p1.x * vv.x + p1.y * vv.y + p1.z * vv.z + p1.w * vv.w;
            o2 += p2.x * vv.x + p2.y * vv.y + p2.z * vv.z + p2.w * vv.w;
            o3 += p3.x * vv.x + p3.y * vv.y + p3.z * vv.z + p3.w * vv.w;
        }
        const int col = h * HD + lane;
        if (n0 + 0 < N_TOK) x_s[(n0 + 0) * XLD + col] = o0;
        if (n0 + 1 < N_TOK) x_s[(n0 + 1) * XLD + col] = o1;
        if (n0 + 2 < N_TOK) x_s[(n0 + 2) * XLD + col] = o2;
        if (n0 + 3 < N_TOK) x_s[(n0 + 3) * XLD + col] = o3;
        __syncwarp();   // protect ap before next task reuses it
    }
    __syncthreads();

    // ---- Phase 4: proj [98,96]x[96,96] + bias, float4 ----------------------
    float* z_s = sm + Q_OFF;   // reuse qT..kT region (19200 floats >= 9800)
    {
        const int r0 = lane, r1 = lane + 32, r2 = lane + 64;
        const int cb = warp * 6;
        float a0[6], a1[6], a2[6];
        #pragma unroll
        for (int c = 0; c < 6; ++c) { a0[c] = 0.f; a1[c] = 0.f; a2[c] = 0.f; }
        const float* wp = proj_w + cb * C_DIM;
        #pragma unroll 3
        for (int kq = 0; kq < C_DIM / 4; ++kq) {
            float4 x0 = *(const float4*)(x_s + r0 * XLD + 4 * kq);
            float4 x1 = *(const float4*)(x_s + r1 * XLD + 4 * kq);
            float4 x2 = *(const float4*)(x_s + r2 * XLD + 4 * kq);
            #pragma unroll
            for (int c = 0; c < 6; ++c) {
                float4 wv = ldg4(wp + c * C_DIM + 4 * kq);
                a0[c] += x0.x * wv.x + x0.y * wv.y + x0.z * wv.z + x0.w * wv.w;
                a1[c] += x1.x * wv.x + x1.y * wv.y + x1.z * wv.z + x1.w * wv.w;
                a2[c] += x2.x * wv.x + x2.y * wv.y + x2.z * wv.z + x2.w * wv.w;
            }
        }
        #pragma unroll
        for (int c = 0; c < 6; ++c) {
            float pb = proj_b[cb + c];
            z_s[r0 * XLD + cb + c] = a0[c] + pb;
            z_s[r1 * XLD + cb + c] = a1[c] + pb;
            z_s[r2 * XLD + cb + c] = a2[c] + pb;
        }
        if (tid < 2 * C_DIM) {          // rows 96,97
            int c = tid % C_DIM;
            int r = 96 + tid / C_DIM;
            float a = 0.f;
            const float* wp2 = proj_w + c * C_DIM;
            #pragma unroll 6
            for (int kq = 0; kq < C_DIM / 4; ++kq) {
                float4 wv = ldg4(wp2 + 4 * kq);
                float4 xv = *(const float4*)(x_s + r * XLD + 4 * kq);
                a += xv.x * wv.x + xv.y * wv.y + xv.z * wv.z + xv.w * wv.w;
            }
            z_s[r * XLD + c] = a + proj_b[c];
        }
    }
    __syncthreads();

    // ---- Phase 5: coalesced float4 store -----------------------------------
    float* ob = out + (size_t)b * (N_TOK * C_DIM);
    for (int idx = tid * 4; idx < N_TOK * C_DIM; idx += NTHREADS * 4) {
        int n = idx / C_DIM, k = idx % C_DIM;
        float4 v = *(const float4*)(z_s + n * XLD + k);
        *(float4*)(ob + idx) = v;
    }
}

extern "C" void kernel_launch(void* const* d_in, const int* in_sizes, int n_in,
                              void* d_out, int out_size) {
    const float* x      = (const float*)d_in[0];
    const float* qkv_w  = (const float*)d_in[1];
    const float* qkv_b  = (const float*)d_in[2];
    const float* proj_w = (const float*)d_in[3];
    const float* proj_b = (const float*)d_in[4];
    const float* table  = (const float*)d_in[5];
    const int*   ridx   = (const int*)d_in[6];
    float* out = (float*)d_out;

    bias_precompute_kernel<<<(NHEAD * N_TOK * N_TOK + 255) / 256, 256>>>(table, ridx);

    cudaFuncSetAttribute(win_attn_kernel,
                         cudaFuncAttributeMaxDynamicSharedMemorySize, SMEM_BYTES);
    win_attn_kernel<<<NWIN, NTHREADS, SMEM_BYTES>>>(x, qkv_w, qkv_b, proj_w, proj_b, out);
}

// round 8
// speedup vs baseline: 2.0324x; 1.1369x over previous
#include <cuda_runtime.h>
#include <cstdint>

// WindowAttention3D fused TF32 mma.sync kernel (one CTA per window).
// B=4096 windows, N=98 tokens (pad 112), C=96, H=3 heads, hd=32.

#define N_TOK 98
#define C_DIM 96
#define NHEAD 3
#define HD    32
#define NWIN  4096
#define MPAD  112          // 7 x m16 tiles
#define SLD   100          // q_s / k_s row stride (100%32=4 -> frag banks 4r+c, cf)
#define PLD   108          // P / x row stride (108%32=12 -> 12r+c, cf)
#define VLD   108          // vT row stride

#define NTHREADS 256
#define NW       8

// SMEM float offsets
#define Q_OFF 0                          // 112*100 = 11200   (q, later y)
#define K_OFF 11200                      // 104*100 = 10400
#define V_OFF 21600                      // 3*32*108 = 10368  (vT[h][d][m])
#define P_OFF 31968                      // 112*108 = 12096   (x, then probs)
#define SMEM_FLOATS 44064
#define SMEM_BYTES  (SMEM_FLOATS * 4)    // 176256 B

__device__ float g_bias[NHEAD * N_TOK * N_TOK];

__global__ void bias_precompute_kernel(const float* __restrict__ table,
                                       const int* __restrict__ ridx) {
    int i = blockIdx.x * blockDim.x + threadIdx.x;
    if (i < NHEAD * N_TOK * N_TOK) {
        int h  = i / (N_TOK * N_TOK);
        int nm = i % (N_TOK * N_TOK);
        g_bias[i] = table[ridx[nm] * NHEAD + h];
    }
}

__device__ __forceinline__ uint32_t f2tf(float f) {
    uint32_t r;
    asm("cvt.rna.tf32.f32 %0, %1;" : "=r"(r) : "f"(f));
    return r;
}
__device__ __forceinline__ float f2tff(float f) { return __uint_as_float(f2tf(f)); }
__device__ __forceinline__ uint32_t fu(float f) { return __float_as_uint(f); }

__device__ __forceinline__ void mma8(float c[4],
                                     uint32_t a0, uint32_t a1, uint32_t a2, uint32_t a3,
                                     uint32_t b0, uint32_t b1) {
    asm volatile(
        "mma.sync.aligned.m16n8k8.row.col.f32.tf32.tf32.f32 "
        "{%0,%1,%2,%3}, {%4,%5,%6,%7}, {%8,%9}, {%0,%1,%2,%3};"
        : "+f"(c[0]), "+f"(c[1]), "+f"(c[2]), "+f"(c[3])
        : "r"(a0), "r"(a1), "r"(a2), "r"(a3), "r"(b0), "r"(b1));
}

__global__ void __launch_bounds__(NTHREADS, 1)
win_attn_kernel(const float* __restrict__ x,
                const float* __restrict__ qkv_w,   // [288][96]
                const float* __restrict__ qkv_b,   // [288]
                const float* __restrict__ proj_w,  // [96][96]
                const float* __restrict__ proj_b,  // [96]
                float* __restrict__ out) {
    extern __shared__ float sm[];
    float* q_s = sm + Q_OFF;   // [112][SLD] q (row-major n x 96), later y
    float* k_s = sm + K_OFF;   // [104][SLD] k
    float* vT  = sm + V_OFF;   // [3][32][VLD] v transposed: [h][d][token]
    float* P   = sm + P_OFF;   // [112][PLD] first x, then probs

    const int tid  = threadIdx.x;
    const int lane = tid & 31;
    const int warp = tid >> 5;
    const int gid  = lane >> 2;   // groupID 0..7
    const int tig  = lane & 3;    // thread-in-group 0..3
    const int b    = blockIdx.x;
    const float* xb = x + (size_t)b * (N_TOK * C_DIM);

    // ---- Phase 0: load x -> P region (TF32-rounded), zero pad rows --------
    for (int i = tid; i < MPAD * C_DIM; i += NTHREADS) {
        int n = i / C_DIM, c = i % C_DIM;
        float v = (n < N_TOK) ? xb[n * C_DIM + c] : 0.f;
        P[n * PLD + c] = f2tff(v);
    }
    __syncthreads();

    // ---- Phase 1: QKV GEMM [112,96] x [96,288] via m16n8k8 -----------------
    // task = n-tile of 8 cols (36 tiles); warp loops 7 m-tiles with B reuse.
    for (int nt = warp; nt < 36; nt += NW) {
        const int n0  = nt * 8;
        const int mat = n0 / C_DIM;            // 0=q 1=k 2=v (tiles never cross)
        const int jj0 = n0 % C_DIM;
        float c[7][4];
        #pragma unroll
        for (int m = 0; m < 7; ++m) { c[m][0]=c[m][1]=c[m][2]=c[m][3]=0.f; }

        #pragma unroll
        for (int kt = 0; kt < 12; ++kt) {
            const int kc = kt * 8 + tig;
            uint32_t b0 = f2tf(qkv_w[(n0 + gid) * C_DIM + kc]);
            uint32_t b1 = f2tf(qkv_w[(n0 + gid) * C_DIM + kc + 4]);
            #pragma unroll
            for (int m = 0; m < 7; ++m) {
                const float* ab = P + (m * 16 + gid) * PLD + kc;
                uint32_t a0 = fu(ab[0]);
                uint32_t a1 = fu(ab[8 * PLD]);
                uint32_t a2 = fu(ab[4]);
                uint32_t a3 = fu(ab[8 * PLD + 4]);
                mma8(c[m], a0, a1, a2, a3, b0, b1);
            }
        }
        const float bv0 = qkv_b[n0 + tig * 2];
        const float bv1 = qkv_b[n0 + tig * 2 + 1];
        #pragma unroll
        for (int m = 0; m < 7; ++m) {
            const int r0 = m * 16 + gid, r1 = r0 + 8;
            const int j0 = jj0 + tig * 2;
            if (mat == 0) {
                q_s[r0 * SLD + j0]     = f2tff(c[m][0] + bv0);
                q_s[r0 * SLD + j0 + 1] = f2tff(c[m][1] + bv1);
                q_s[r1 * SLD + j0]     = f2tff(c[m][2] + bv0);
                q_s[r1 * SLD + j0 + 1] = f2tff(c[m][3] + bv1);
            } else if (mat == 1) {
                if (r0 < 104) {
                    k_s[r0 * SLD + j0]     = f2tff(c[m][0] + bv0);
                    k_s[r0 * SLD + j0 + 1] = f2tff(c[m][1] + bv1);
                }
                if (r1 < 104) {
                    k_s[r1 * SLD + j0]     = f2tff(c[m][2] + bv0);
                    k_s[r1 * SLD + j0 + 1] = f2tff(c[m][3] + bv1);
                }
            } else {
                const int h  = jj0 / HD;
                const int d0 = (jj0 % HD) + tig * 2;
                float* vb = vT + h * (HD * VLD);
                if (r0 < 104) {
                    vb[d0 * VLD + r0]       = f2tff(c[m][0] + bv0);
                    vb[(d0 + 1) * VLD + r0] = f2tff(c[m][1] + bv1);
                }
                if (r1 < 104) {
                    vb[d0 * VLD + r1]       = f2tff(c[m][2] + bv0);
                    vb[(d0 + 1) * VLD + r1] = f2tff(c[m][3] + bv1);
                }
            }
        }
    }
    __syncthreads();

    // ---- Phase 2: per head: scores -> softmax(+bias) -> AV -----------------
    const float scale = 0.17677669529663687f;   // 32^-0.5
    for (int h = 0; h < NHEAD; ++h) {
        const int hc = h * HD;

        // scores S = q @ k^T: 7 m-tiles x 13 n-tiles, K=32
        for (int t = warp; t < 7 * 13; t += NW) {
            const int mt = t / 13, nt = t % 13;
            float c[4] = {0.f, 0.f, 0.f, 0.f};
            const float* ab0 = q_s + (mt * 16 + gid) * SLD + hc + tig;
            const float* bb0 = k_s + (nt * 8 + gid) * SLD + hc + tig;
            #pragma unroll
            for (int kt = 0; kt < 4; ++kt) {
                const int kc = kt * 8;
                uint32_t a0 = fu(ab0[kc]);
                uint32_t a1 = fu(ab0[kc + 8 * SLD]);
                uint32_t a2 = fu(ab0[kc + 4]);
                uint32_t a3 = fu(ab0[kc + 8 * SLD + 4]);
                uint32_t b0 = fu(bb0[kc]);
                uint32_t b1 = fu(bb0[kc + 4]);
                mma8(c, a0, a1, a2, a3, b0, b1);
            }
            const int r0 = mt * 16 + gid, c0 = nt * 8 + tig * 2;
            P[r0 * PLD + c0]           = c[0] * scale;
            P[r0 * PLD + c0 + 1]       = c[1] * scale;
            P[(r0 + 8) * PLD + c0]     = c[2] * scale;
            P[(r0 + 8) * PLD + c0 + 1] = c[3] * scale;
        }
        __syncthreads();

        // softmax over valid 98 cols, bias added here (coalesced row reads)
        for (int r = warp; r < N_TOK; r += NW) {
            const float* brow = g_bias + (h * N_TOK + r) * N_TOK;
            float* prow = P + r * PLD;
            float t0 = prow[lane]      + brow[lane];
            float t1 = prow[lane + 32] + brow[lane + 32];
            float t2 = prow[lane + 64] + brow[lane + 64];
            float t3 = -1e30f;
            if (lane < 2) t3 = prow[lane + 96] + brow[lane + 96];  // predicated, no OOB
            float mx = fmaxf(fmaxf(t0, t1), fmaxf(t2, t3));
            #pragma unroll
            for (int o = 16; o; o >>= 1) mx = fmaxf(mx, __shfl_xor_sync(0xffffffffu, mx, o));
            float e0 = __expf(t0 - mx), e1 = __expf(t1 - mx), e2 = __expf(t2 - mx);
            float e3 = (lane < 2) ? __expf(t3 - mx) : 0.f;
            float sum = e0 + e1 + e2 + e3;
            #pragma unroll
            for (int o = 16; o; o >>= 1) sum += __shfl_xor_sync(0xffffffffu, sum, o);
            float inv = 1.0f / sum;
            prow[lane]      = f2tff(e0 * inv);
            prow[lane + 32] = f2tff(e1 * inv);
            prow[lane + 64] = f2tff(e2 * inv);
            // pad cols 96..107 ONLY (stay inside this row's PLD=108 stride!):
            // cols 96,97 real probs; cols 98..103 must be 0 for the AV K-tiles.
            if (lane < 12)
                prow[lane + 96] = (lane < 2) ? f2tff(e3 * inv) : 0.f;
        }
        __syncthreads();

        // AV: y[112,32] = P[112,104] @ V[104,32]; B from vT (col-major view)
        for (int t = warp; t < 7 * 4; t += NW) {
            const int mt = t >> 2, nt = t & 3;
            float c[4] = {0.f, 0.f, 0.f, 0.f};
            const float* ab0 = P + (mt * 16 + gid) * PLD + tig;
            const float* bb0 = vT + h * (HD * VLD) + (nt * 8 + gid) * VLD + tig;
            #pragma unroll
            for (int kt = 0; kt < 13; ++kt) {
                const int kc = kt * 8;
                uint32_t a0 = fu(ab0[kc]);
                uint32_t a1 = fu(ab0[kc + 8 * PLD]);
                uint32_t a2 = fu(ab0[kc + 4]);
                uint32_t a3 = fu(ab0[kc + 8 * PLD + 4]);
                uint32_t b0 = fu(bb0[kc]);
                uint32_t b1 = fu(bb0[kc + 4]);
                mma8(c, a0, a1, a2, a3, b0, b1);
            }
            // write y into q_s head-h column slice (q slice dead after scores)
            const int r0 = mt * 16 + gid;
            const int cc = hc + nt * 8 + tig * 2;
            q_s[r0 * SLD + cc]           = f2tff(c[0]);
            q_s[r0 * SLD + cc + 1]       = f2tff(c[1]);
            q_s[(r0 + 8) * SLD + cc]     = f2tff(c[2]);
            q_s[(r0 + 8) * SLD + cc + 1] = f2tff(c[3]);
        }
        __syncthreads();
    }

    // ---- Phase 3: proj [112,96] x [96,96] + bias -> global -----------------
    float* ob = out + (size_t)b * (N_TOK * C_DIM);
    for (int t = warp; t < 7 * 12; t += NW) {
        const int mt = t / 12, nt = t % 12;
        float c[4] = {0.f, 0.f, 0.f, 0.f};
        const float* ab0 = q_s + (mt * 16 + gid) * SLD + tig;
        const int wrow = (nt * 8 + gid) * C_DIM + tig;
        #pragma unroll
        for (int kt = 0; kt < 12; ++kt) {
            const int kc = kt * 8;
            uint32_t a0 = fu(ab0[kc]);
            uint32_t a1 = fu(ab0[kc + 8 * SLD]);
            uint32_t a2 = fu(ab0[kc + 4]);
            uint32_t a3 = fu(ab0[kc + 8 * SLD + 4]);
            uint32_t b0 = f2tf(proj_w[wrow + kc]);
            uint32_t b1 = f2tf(proj_w[wrow + kc + 4]);
            mma8(c, a0, a1, a2, a3, b0, b1);
        }
        const int r0 = mt * 16 + gid, cc = nt * 8 + tig * 2;
        const float pb0 = proj_b[cc], pb1 = proj_b[cc + 1];
        if (r0 < N_TOK) {
            ob[r0 * C_DIM + cc]     = c[0] + pb0;
            ob[r0 * C_DIM + cc + 1] = c[1] + pb1;
        }
        if (r0 + 8 < N_TOK) {
            ob[(r0 + 8) * C_DIM + cc]     = c[2] + pb0;
            ob[(r0 + 8) * C_DIM + cc + 1] = c[3] + pb1;
        }
    }
}

extern "C" void kernel_launch(void* const* d_in, const int* in_sizes, int n_in,
                              void* d_out, int out_size) {
    const float* x      = (const float*)d_in[0];
    const float* qkv_w  = (const float*)d_in[1];
    const float* qkv_b  = (const float*)d_in[2];
    const float* proj_w = (const float*)d_in[3];
    const float* proj_b = (const float*)d_in[4];
    const float* table  = (const float*)d_in[5];
    const int*   ridx   = (const int*)d_in[6];
    float* out = (float*)d_out;

    bias_precompute_kernel<<<(NHEAD * N_TOK * N_TOK + 255) / 256, 256>>>(table, ridx);

    cudaFuncSetAttribute(win_attn_kernel,
                         cudaFuncAttributeMaxDynamicSharedMemorySize, SMEM_BYTES);
    win_attn_kernel<<<NWIN, NTHREADS, SMEM_BYTES>>>(x, qkv_w, qkv_b, proj_w, proj_b, out);
}

// round 9
// speedup vs baseline: 2.5155x; 1.2377x over previous
#include <cuda_runtime.h>
#include <cstdint>

// WindowAttention3D fused TF32 mma.sync kernel (one CTA per window).
// B=4096 windows, N=98 tokens (pad 112), C=96, H=3 heads, hd=32.
// R9: 512 threads (16 warps), wider register tiles, fewer LDS/MMA.

#define N_TOK 98
#define C_DIM 96
#define NHEAD 3
#define HD    32
#define NWIN  4096
#define MPAD  112          // 7 x m16 tiles
#define SLD   100          // q_s / k_s row stride
#define PLD   108          // P row stride
#define VLD   108          // vT row stride

#define NTHREADS 512
#define NW       16

// SMEM float offsets
#define Q_OFF 0                          // 112*100 = 11200   (q, later y)
#define K_OFF 11200                      // 104*100 = 10400
#define V_OFF 21600                      // 3*32*108 = 10368  (vT[h][d][m])
#define P_OFF 31968                      // 112*108 = 12096   (x, then probs)
#define SMEM_FLOATS 44064
#define SMEM_BYTES  (SMEM_FLOATS * 4)    // 176256 B

__device__ float g_bias[NHEAD * N_TOK * N_TOK];

__global__ void bias_precompute_kernel(const float* __restrict__ table,
                                       const int* __restrict__ ridx) {
    int i = blockIdx.x * blockDim.x + threadIdx.x;
    if (i < NHEAD * N_TOK * N_TOK) {
        int h  = i / (N_TOK * N_TOK);
        int nm = i % (N_TOK * N_TOK);
        g_bias[i] = table[ridx[nm] * NHEAD + h];
    }
}

__device__ __forceinline__ uint32_t f2tf(float f) {
    uint32_t r;
    asm("cvt.rna.tf32.f32 %0, %1;" : "=r"(r) : "f"(f));
    return r;
}
__device__ __forceinline__ float f2tff(float f) { return __uint_as_float(f2tf(f)); }
__device__ __forceinline__ uint32_t fu(float f) { return __float_as_uint(f); }

__device__ __forceinline__ void mma8(float c[4],
                                     uint32_t a0, uint32_t a1, uint32_t a2, uint32_t a3,
                                     uint32_t b0, uint32_t b1) {
    asm volatile(
        "mma.sync.aligned.m16n8k8.row.col.f32.tf32.tf32.f32 "
        "{%0,%1,%2,%3}, {%4,%5,%6,%7}, {%8,%9}, {%0,%1,%2,%3};"
        : "+f"(c[0]), "+f"(c[1]), "+f"(c[2]), "+f"(c[3])
        : "r"(a0), "r"(a1), "r"(a2), "r"(a3), "r"(b0), "r"(b1));
}

__global__ void __launch_bounds__(NTHREADS, 1)
win_attn_kernel(const float* __restrict__ x,
                const float* __restrict__ qkv_w,   // [288][96]
                const float* __restrict__ qkv_b,   // [288]
                const float* __restrict__ proj_w,  // [96][96]
                const float* __restrict__ proj_b,  // [96]
                float* __restrict__ out) {
    extern __shared__ float sm[];
    float* q_s = sm + Q_OFF;   // [112][SLD] q*scale (row-major n x 96), later y
    float* k_s = sm + K_OFF;   // [104][SLD] k
    float* vT  = sm + V_OFF;   // [3][32][VLD] v transposed: [h][d][token]
    float* P   = sm + P_OFF;   // [112][PLD] first x, then scores/probs

    const int tid  = threadIdx.x;
    const int lane = tid & 31;
    const int warp = tid >> 5;
    const int gid  = lane >> 2;   // groupID 0..7
    const int tig  = lane & 3;    // thread-in-group 0..3
    const int b    = blockIdx.x;
    const float* xb = x + (size_t)b * (N_TOK * C_DIM);

    // ---- Phase 0: load x -> P (TF32-rounded, float4), zero pad rows --------
    for (int i = tid * 4; i < N_TOK * C_DIM; i += NTHREADS * 4) {
        float4 v = *(const float4*)(xb + i);
        int n = i / C_DIM, c = i % C_DIM;
        float4 r = make_float4(f2tff(v.x), f2tff(v.y), f2tff(v.z), f2tff(v.w));
        *(float4*)(P + n * PLD + c) = r;
    }
    for (int i = tid; i < (MPAD - N_TOK) * C_DIM; i += NTHREADS) {
        int n = N_TOK + i / C_DIM, c = i % C_DIM;
        P[n * PLD + c] = 0.f;
    }
    __syncthreads();

    const float scale = 0.17677669529663687f;   // 32^-0.5

    // ---- Phase 1: QKV GEMM [112,96] x [96,288]; task = (n-tile, m-half) ----
    for (int t = warp; t < 72; t += NW) {
        const int nt  = t >> 1;
        const int mtbase = (t & 1) * 4;          // m-tiles mtbase..mtbase+3 (<7)
        const int n0  = nt * 8;
        const int mat = n0 / C_DIM;              // 0=q 1=k 2=v
        const int jj0 = n0 % C_DIM;
        float c[4][4];
        #pragma unroll
        for (int mi = 0; mi < 4; ++mi) { c[mi][0]=c[mi][1]=c[mi][2]=c[mi][3]=0.f; }

        const float* wbase = qkv_w + (n0 + gid) * C_DIM;
        #pragma unroll
        for (int kt = 0; kt < 12; ++kt) {
            const int kc = kt * 8 + tig;
            uint32_t b0 = f2tf(wbase[kc]);
            uint32_t b1 = f2tf(wbase[kc + 4]);
            #pragma unroll
            for (int mi = 0; mi < 4; ++mi) {
                const int mt = mtbase + mi;
                if (mt < 7) {
                    const float* ab = P + (mt * 16 + gid) * PLD + kc;
                    mma8(c[mi], fu(ab[0]), fu(ab[8 * PLD]), fu(ab[4]), fu(ab[8 * PLD + 4]),
                         b0, b1);
                }
            }
        }
        const float bv0 = qkv_b[n0 + tig * 2];
        const float bv1 = qkv_b[n0 + tig * 2 + 1];
        #pragma unroll
        for (int mi = 0; mi < 4; ++mi) {
            const int mt = mtbase + mi;
            if (mt < 7) {
                const int r0 = mt * 16 + gid, r1 = r0 + 8;
                const int j0 = jj0 + tig * 2;
                if (mat == 0) {      // q: fold softmax scale in here
                    q_s[r0 * SLD + j0]     = f2tff((c[mi][0] + bv0) * scale);
                    q_s[r0 * SLD + j0 + 1] = f2tff((c[mi][1] + bv1) * scale);
                    q_s[r1 * SLD + j0]     = f2tff((c[mi][2] + bv0) * scale);
                    q_s[r1 * SLD + j0 + 1] = f2tff((c[mi][3] + bv1) * scale);
                } else if (mat == 1) {
                    if (r0 < 104) {
                        k_s[r0 * SLD + j0]     = f2tff(c[mi][0] + bv0);
                        k_s[r0 * SLD + j0 + 1] = f2tff(c[mi][1] + bv1);
                    }
                    if (r1 < 104) {
                        k_s[r1 * SLD + j0]     = f2tff(c[mi][2] + bv0);
                        k_s[r1 * SLD + j0 + 1] = f2tff(c[mi][3] + bv1);
                    }
                } else {
                    const int h  = jj0 / HD;
                    const int d0 = (jj0 % HD) + tig * 2;
                    float* vb = vT + h * (HD * VLD);
                    if (r0 < 104) {
                        vb[d0 * VLD + r0]       = f2tff(c[mi][0] + bv0);
                        vb[(d0 + 1) * VLD + r0] = f2tff(c[mi][1] + bv1);
                    }
                    if (r1 < 104) {
                        vb[d0 * VLD + r1]       = f2tff(c[mi][2] + bv0);
                        vb[(d0 + 1) * VLD + r1] = f2tff(c[mi][3] + bv1);
                    }
                }
            }
        }
    }
    __syncthreads();

    // ---- Phase 2: per head: scores -> softmax(+bias) -> AV -----------------
    for (int h = 0; h < NHEAD; ++h) {
        const int hc = h * HD;

        // scores S = (q*scale) @ k^T: task = (m-tile, n-quad), K=32
        for (int t = warp; t < 28; t += NW) {
            const int mt = t >> 2, ntq = t & 3;
            float c[4][4];
            #pragma unroll
            for (int ni = 0; ni < 4; ++ni) { c[ni][0]=c[ni][1]=c[ni][2]=c[ni][3]=0.f; }
            const float* ab0 = q_s + (mt * 16 + gid) * SLD + hc + tig;
            #pragma unroll
            for (int kt = 0; kt < 4; ++kt) {
                const int kc = kt * 8;
                uint32_t a0 = fu(ab0[kc]);
                uint32_t a1 = fu(ab0[kc + 8 * SLD]);
                uint32_t a2 = fu(ab0[kc + 4]);
                uint32_t a3 = fu(ab0[kc + 8 * SLD + 4]);
                #pragma unroll
                for (int ni = 0; ni < 4; ++ni) {
                    const int nt = ntq * 4 + ni;
                    if (nt < 13) {
                        const float* bb = k_s + (nt * 8 + gid) * SLD + hc + tig + kc;
                        mma8(c[ni], a0, a1, a2, a3, fu(bb[0]), fu(bb[4]));
                    }
                }
            }
            const int r0 = mt * 16 + gid;
            #pragma unroll
            for (int ni = 0; ni < 4; ++ni) {
                const int nt = ntq * 4 + ni;
                if (nt < 13) {
                    const int c0 = nt * 8 + tig * 2;
                    P[r0 * PLD + c0]           = c[ni][0];
                    P[r0 * PLD + c0 + 1]       = c[ni][1];
                    P[(r0 + 8) * PLD + c0]     = c[ni][2];
                    P[(r0 + 8) * PLD + c0 + 1] = c[ni][3];
                }
            }
        }
        __syncthreads();

        // softmax over valid 98 cols, bias added here
        for (int r = warp; r < N_TOK; r += NW) {
            const float* brow = g_bias + (h * N_TOK + r) * N_TOK;
            float* prow = P + r * PLD;
            float t0 = prow[lane]      + brow[lane];
            float t1 = prow[lane + 32] + brow[lane + 32];
            float t2 = prow[lane + 64] + brow[lane + 64];
            float t3 = -1e30f;
            if (lane < 2) t3 = prow[lane + 96] + brow[lane + 96];
            float mx = fmaxf(fmaxf(t0, t1), fmaxf(t2, t3));
            #pragma unroll
            for (int o = 16; o; o >>= 1) mx = fmaxf(mx, __shfl_xor_sync(0xffffffffu, mx, o));
            float e0 = __expf(t0 - mx), e1 = __expf(t1 - mx), e2 = __expf(t2 - mx);
            float e3 = (lane < 2) ? __expf(t3 - mx) : 0.f;
            float sum = e0 + e1 + e2 + e3;
            #pragma unroll
            for (int o = 16; o; o >>= 1) sum += __shfl_xor_sync(0xffffffffu, sum, o);
            float inv = 1.0f / sum;
            prow[lane]      = f2tff(e0 * inv);
            prow[lane + 32] = f2tff(e1 * inv);
            prow[lane + 64] = f2tff(e2 * inv);
            // pad cols 96..107 ONLY (inside this row's PLD stride):
            if (lane < 12)
                prow[lane + 96] = (lane < 2) ? f2tff(e3 * inv) : 0.f;
        }
        __syncthreads();

        // AV: y = P[112,104] @ V[104,32]; task = (m-pair, n-tile) -> 16 tasks
        for (int t = warp; t < 16; t += NW) {
            const int mtp = t >> 2, nt = t & 3;
            float c[2][4];
            #pragma unroll
            for (int mi = 0; mi < 2; ++mi) { c[mi][0]=c[mi][1]=c[mi][2]=c[mi][3]=0.f; }
            const float* bb0 = vT + h * (HD * VLD) + (nt * 8 + gid) * VLD + tig;
            #pragma unroll
            for (int kt = 0; kt < 13; ++kt) {
                const int kc = kt * 8;
                uint32_t b0 = fu(bb0[kc]);
                uint32_t b1 = fu(bb0[kc + 4]);
                #pragma unroll
                for (int mi = 0; mi < 2; ++mi) {
                    const int mt = mtp * 2 + mi;
                    if (mt < 7) {
                        const float* ab = P + (mt * 16 + gid) * PLD + tig + kc;
                        mma8(c[mi], fu(ab[0]), fu(ab[8 * PLD]), fu(ab[4]), fu(ab[8 * PLD + 4]),
                             b0, b1);
                    }
                }
            }
            #pragma unroll
            for (int mi = 0; mi < 2; ++mi) {
                const int mt = mtp * 2 + mi;
                if (mt < 7) {
                    const int r0 = mt * 16 + gid;
                    const int cc = hc + nt * 8 + tig * 2;
                    q_s[r0 * SLD + cc]           = f2tff(c[mi][0]);
                    q_s[r0 * SLD + cc + 1]       = f2tff(c[mi][1]);
                    q_s[(r0 + 8) * SLD + cc]     = f2tff(c[mi][2]);
                    q_s[(r0 + 8) * SLD + cc + 1] = f2tff(c[mi][3]);
                }
            }
        }
        __syncthreads();
    }

    // ---- Phase 3: proj [112,96] x [96,96] + bias; task = (m-tile, n-pair) --
    float* ob = out + (size_t)b * (N_TOK * C_DIM);
    for (int t = warp; t < 42; t += NW) {
        const int mt = t / 6, ntp = t % 6;
        float c[2][4];
        #pragma unroll
        for (int ni = 0; ni < 2; ++ni) { c[ni][0]=c[ni][1]=c[ni][2]=c[ni][3]=0.f; }
        const float* ab0 = q_s + (mt * 16 + gid) * SLD + tig;
        #pragma unroll
        for (int kt = 0; kt < 12; ++kt) {
            const int kc = kt * 8;
            uint32_t a0 = fu(ab0[kc]);
            uint32_t a1 = fu(ab0[kc + 8 * SLD]);
            uint32_t a2 = fu(ab0[kc + 4]);
            uint32_t a3 = fu(ab0[kc + 8 * SLD + 4]);
            #pragma unroll
            for (int ni = 0; ni < 2; ++ni) {
                const int nt = ntp * 2 + ni;
                const float* wp = proj_w + (nt * 8 + gid) * C_DIM + tig + kc;
                mma8(c[ni], a0, a1, a2, a3, f2tf(wp[0]), f2tf(wp[4]));
            }
        }
        const int r0 = mt * 16 + gid;
        #pragma unroll
        for (int ni = 0; ni < 2; ++ni) {
            const int nt = ntp * 2 + ni;
            const int cc = nt * 8 + tig * 2;
            const float pb0 = proj_b[cc], pb1 = proj_b[cc + 1];
            if (r0 < N_TOK) {
                ob[r0 * C_DIM + cc]     = c[ni][0] + pb0;
                ob[r0 * C_DIM + cc + 1] = c[ni][1] + pb1;
            }
            if (r0 + 8 < N_TOK) {
                ob[(r0 + 8) * C_DIM + cc]     = c[ni][2] + pb0;
                ob[(r0 + 8) * C_DIM + cc + 1] = c[ni][3] + pb1;
            }
        }
    }
}

extern "C" void kernel_launch(void* const* d_in, const int* in_sizes, int n_in,
                              void* d_out, int out_size) {
    const float* x      = (const float*)d_in[0];
    const float* qkv_w  = (const float*)d_in[1];
    const float* qkv_b  = (const float*)d_in[2];
    const float* proj_w = (const float*)d_in[3];
    const float* proj_b = (const float*)d_in[4];
    const float* table  = (const float*)d_in[5];
    const int*   ridx   = (const int*)d_in[6];
    float* out = (float*)d_out;

    bias_precompute_kernel<<<(NHEAD * N_TOK * N_TOK + 255) / 256, 256>>>(table, ridx);

    cudaFuncSetAttribute(win_attn_kernel,
                         cudaFuncAttributeMaxDynamicSharedMemorySize, SMEM_BYTES);
    win_attn_kernel<<<NWIN, NTHREADS, SMEM_BYTES>>>(x, qkv_w, qkv_b, proj_w, proj_b, out);
}